// round 2
// baseline (speedup 1.0000x reference)
#include <cuda_runtime.h>
#include <math.h>

// ============================================================================
// CKConv via FFT convolution.
//   h1[l,m] = sin(30*rel[l]*W1[m]);  h2[l,j] = sin(30*Σ_m h1[l,m]W2[m,j])
//   ker[o,i,s] = Σ_m h2[s,m] W3[m,o*64+i]
//   out[b,o,t] = Σ_i Σ_{u≤t} x[b,i,u] ker[o,i,u+2047-t]
//              = Σ_i (x[b,i] * Krev[o,i])[t],  Krev[o,i,d]=ker[o,i,2047-d]
// FFT (N=4096) both sides; kernel spectrum built directly from the 128
// SIREN feature spectra:  Kf[f,i,o] = Σ_m W3[m,o*64+i] * Gf[m,f]
// where g[d,m] = h2[2047-d,m] (zero padded). Then per-bin 64x64 complex mix,
// Hermitian-extend, inverse FFT, take real part / N.
// ============================================================================

#define LL     2048
#define NFFT   4096
#define HID    128
#define NBINS  2049   // NFFT/2 + 1

// ---- scratch (static __device__ globals; no runtime allocation) ----
__device__ float  d_h2T[HID * LL];         // [m][l]
__device__ float  d_W3p[HID * 4096];       // [m][n'] with n' = i*64+o
__device__ float2 d_tw[NFFT / 2];          // twiddles e^{-2pi i j / N}
__device__ float2 d_Gf[HID * NFFT];        // [m][f]
__device__ float2 d_Xf[128 * NFFT];        // [b*64+i][f]
__device__ float2 d_Kf[NBINS * 4096];      // [f][i*64+o]   (~67 MB)
__device__ float2 d_Outf[128 * NBINS];     // [b*64+o][f]

// ---------------------------------------------------------------- twiddles --
__global__ void init_tw_kernel() {
    int j = blockIdx.x * blockDim.x + threadIdx.x;
    if (j < NFFT / 2) {
        float a = (float)(2.0 * 3.14159265358979323846 / (double)NFFT) * (float)j;
        float s, c;
        sincosf(a, &s, &c);
        d_tw[j] = make_float2(c, -s);
    }
}

// ------------------------------------------------- W3 permutation: n -> n' --
// W3p[m][n'] = W3[m][(n'&63)*64 + (n'>>6)]  so that n' = i*64+o maps to
// W3[m][o*64+i]. Makes the K4 GEMM B-tile loads coalesced.
__global__ void perm_w3_kernel(const float* __restrict__ W3) {
    int idx = blockIdx.x * blockDim.x + threadIdx.x;   // < 128*4096
    int m  = idx >> 12;
    int np = idx & 4095;
    d_W3p[idx] = W3[(m << 12) + ((np & 63) << 6) + (np >> 6)];
}

// ------------------------------------------------------------ SIREN stages --
__global__ void gen_h2_kernel(const float* __restrict__ W1,
                              const float* __restrict__ W2) {
    int l = blockIdx.x;     // 0..2047
    int j = threadIdx.x;    // 0..127
    __shared__ float h1[HID];
    float rel = -1.0f + 2.0f * (float)l / 2047.0f;
    h1[j] = sinf(30.0f * rel * W1[j]);
    __syncthreads();
    float acc = 0.0f;
#pragma unroll 16
    for (int m = 0; m < HID; m++)
        acc += h1[m] * W2[m * HID + j];
    d_h2T[j * LL + l] = sinf(30.0f * acc);   // transposed: [m][l]
}

// ----------------------------------------------------------- in-place FFT --
// Radix-2 DIT, N=4096, input pre-permuted (bit-reversed load), natural-order
// output. 256 threads, 8 butterflies/thread/stage, 12 stages.
__device__ __forceinline__ void fft_core(float2* buf) {
    int tid = threadIdx.x;
    int hshift = 0;
    for (int len = 2; len <= NFFT; len <<= 1, hshift++) {
        int half = len >> 1;
        int tw_step = NFFT >> (hshift + 1);
        __syncthreads();
#pragma unroll
        for (int k = 0; k < 8; k++) {
            int bf = tid + (k << 8);                 // 0..2047
            int j  = bf & (half - 1);
            int i0 = ((bf >> hshift) << (hshift + 1)) + j;
            int i1 = i0 + half;
            float2 w = d_tw[j * tw_step];
            float2 u = buf[i0];
            float2 v = buf[i1];
            float2 vw = make_float2(v.x * w.x - v.y * w.y,
                                    v.x * w.y + v.y * w.x);
            buf[i0] = make_float2(u.x + vw.x, u.y + vw.y);
            buf[i1] = make_float2(u.x - vw.x, u.y - vw.y);
        }
    }
    __syncthreads();
}

// FFT of time-reversed, zero-padded SIREN features: g[d] = h2[2047-d]
__global__ void fft_g_kernel() {
    __shared__ float2 buf[NFFT];
    int m = blockIdx.x;   // 0..127
    for (int d = threadIdx.x; d < NFFT; d += 256) {
        int src = __brev(d) >> 20;   // 12-bit reversal
        float v = (src < LL) ? d_h2T[m * LL + (LL - 1 - src)] : 0.0f;
        buf[d] = make_float2(v, 0.0f);
    }
    fft_core(buf);
    for (int f = threadIdx.x; f < NFFT; f += 256)
        d_Gf[m * NFFT + f] = buf[f];
}

// FFT of zero-padded inputs x[b,i,:]
__global__ void fft_x_kernel(const float* __restrict__ x) {
    __shared__ float2 buf[NFFT];
    int r = blockIdx.x;   // b*64+i, 0..127
    for (int d = threadIdx.x; d < NFFT; d += 256) {
        int src = __brev(d) >> 20;
        float v = (src < LL) ? x[r * LL + src] : 0.0f;
        buf[d] = make_float2(v, 0.0f);
    }
    fft_core(buf);
    for (int f = threadIdx.x; f < NFFT; f += 256)
        d_Xf[r * NFFT + f] = buf[f];
}

// ------------------------------------------ K4: kernel spectrum (the GEMM) --
// Kf[f][n'] = Σ_m W3p[m][n'] * Gf[m][f]   (complex acc, real B), f=0..2048.
// Block tile 64(f) x 64(n'), 256 threads, 4x4 per thread, m-chunks of 16.
__global__ void k4_gemm_kernel() {
    __shared__ float2 As[16][64];   // [mm][f]
    __shared__ float  Bs[16][64];   // [mm][n']
    int n0 = blockIdx.x * 64;
    int f0 = blockIdx.y * 64;
    int tx = threadIdx.x & 15;
    int ty = threadIdx.x >> 4;
    float aR[4][4] = {}, aI[4][4] = {};

    for (int m0 = 0; m0 < HID; m0 += 16) {
        __syncthreads();
#pragma unroll
        for (int k = 0; k < 4; k++) {
            int idx = threadIdx.x + (k << 8);   // 0..1023
            int mm = idx >> 6, ff = idx & 63;
            // f0+ff can exceed 2048 but stays < 4096: in-bounds read, store guarded
            As[mm][ff] = d_Gf[(m0 + mm) * NFFT + f0 + ff];
            Bs[mm][ff] = d_W3p[(m0 + mm) * 4096 + n0 + ff];
        }
        __syncthreads();
#pragma unroll
        for (int mm = 0; mm < 16; mm++) {
            float2 a[4];
            float  b[4];
#pragma unroll
            for (int r = 0; r < 4; r++) a[r] = As[mm][ty * 4 + r];
            float4 bb = *(const float4*)&Bs[mm][tx * 4];
            b[0] = bb.x; b[1] = bb.y; b[2] = bb.z; b[3] = bb.w;
#pragma unroll
            for (int r = 0; r < 4; r++)
#pragma unroll
                for (int c = 0; c < 4; c++) {
                    aR[r][c] += a[r].x * b[c];
                    aI[r][c] += a[r].y * b[c];
                }
        }
    }
#pragma unroll
    for (int r = 0; r < 4; r++) {
        int f = f0 + ty * 4 + r;
        if (f < NBINS) {
#pragma unroll
            for (int c = 0; c < 4; c++)
                d_Kf[f * 4096 + n0 + tx * 4 + c] = make_float2(aR[r][c], aI[r][c]);
        }
    }
}

// ---------------------------------------- K5: per-bin 64x64 complex mixing --
// Outf[b,o,f] = Σ_i Xf[b,i,f] * Kf[f][i*64+o]
__global__ void k5_mix_kernel() {
    __shared__ float2 Xs[128];
    int f = blockIdx.x;          // 0..2048
    int t = threadIdx.x;         // 0..127
    Xs[t] = d_Xf[t * NFFT + f];
    __syncthreads();
    int b = t >> 6, o = t & 63;
    const float2* kf = &d_Kf[f * 4096 + o];
    const float2* xs = &Xs[b * 64];
    float ar = 0.0f, ai = 0.0f;
#pragma unroll 8
    for (int i = 0; i < 64; i++) {
        float2 xv = xs[i];
        float2 kv = kf[i * 64];
        ar += xv.x * kv.x - xv.y * kv.y;
        ai += xv.x * kv.y + xv.y * kv.x;
    }
    d_Outf[t * NBINS + f] = make_float2(ar, ai);
}

// --------------------------------- inverse FFT (Hermitian extend + conj) ---
// y = Re(FFT(conj(Outf_full)))/N ; Outf_full[f>2048] = conj(Outf[4096-f]).
__global__ void fft_inv_kernel(float* __restrict__ out) {
    __shared__ float2 buf[NFFT];
    int r = blockIdx.x;   // b*64+o, 0..127
    for (int d = threadIdx.x; d < NFFT; d += 256) {
        int src = __brev(d) >> 20;
        float2 v;
        if (src <= 2048) {
            float2 tval = d_Outf[r * NBINS + src];
            v = make_float2(tval.x, -tval.y);          // conj
        } else {
            v = d_Outf[r * NBINS + (NFFT - src)];      // conj(conj(.)) = .
        }
        buf[d] = v;
    }
    fft_core(buf);
    const float inv = 1.0f / (float)NFFT;
    for (int t = threadIdx.x; t < LL; t += 256)
        out[r * LL + t] = buf[t].x * inv;
}

// ============================================================================
extern "C" void kernel_launch(void* const* d_in, const int* in_sizes, int n_in,
                              void* d_out, int out_size) {
    (void)in_sizes; (void)n_in; (void)out_size;
    const float* x  = (const float*)d_in[0];
    const float* W1 = (const float*)d_in[1];
    const float* W2 = (const float*)d_in[2];
    const float* W3 = (const float*)d_in[3];
    float* out = (float*)d_out;

    init_tw_kernel<<<8, 256>>>();
    perm_w3_kernel<<<2048, 256>>>(W3);
    gen_h2_kernel<<<2048, 128>>>(W1, W2);
    fft_g_kernel<<<128, 256>>>();
    fft_x_kernel<<<128, 256>>>(x);
    k4_gemm_kernel<<<dim3(64, 33), 256>>>();
    k5_mix_kernel<<<NBINS, 128>>>();
    fft_inv_kernel<<<128, 256>>>(out);
}

// round 3
// speedup vs baseline: 1.7033x; 1.7033x over previous
#include <cuda_runtime.h>
#include <math.h>

// ============================================================================
// CKConv via FFT convolution + tf32 tensor-core kernel-spectrum GEMM.
//   out[b,o,t] = Σ_i (x[b,i] * Krev[o,i])[t]
//   Kf[f,i,o]  = Σ_m W3[m,o*64+i] · Gf[m,f],  Gf = FFT(time-reversed SIREN feats)
// Pipeline: SIREN -> radix-4 FFTs (g, x) -> tf32 MMA (Kf) -> per-bin 64x64
// complex mix -> Hermitian inverse FFT.
// ============================================================================

#define LL     2048
#define NFFT   4096
#define HID    128
#define NBINS  2049   // NFFT/2 + 1

// ---- scratch (static __device__ globals; no runtime allocation) ----
__device__ float  d_h2T[HID * LL];         // [m][l]
__device__ float  d_W3p[HID * 4096];       // [m][n'] n' = i*64+o, tf32-rounded
__device__ float2 d_tw4[NFFT];             // e^{-2pi i j / N}, j < N
__device__ float2 d_Gf[HID * NFFT];        // [m][f], tf32-rounded
__device__ float2 d_Xf[128 * NFFT];        // [b*64+i][f]
__device__ float2 d_Kf[NBINS * 4096];      // [f][i*64+o]
__device__ float2 d_Outf[128 * NBINS];     // [b*64+o][f]

__device__ __forceinline__ float to_tf32(float x) {
    unsigned u;
    asm("cvt.rna.tf32.f32 %0, %1;" : "=r"(u) : "f"(x));
    return __uint_as_float(u);
}

// ---------------------------------------------------------------- twiddles --
__global__ void init_tw_kernel() {
    int j = blockIdx.x * blockDim.x + threadIdx.x;
    if (j < NFFT) {
        double a = 2.0 * 3.14159265358979323846 * (double)j / (double)NFFT;
        d_tw4[j] = make_float2((float)cos(a), (float)(-sin(a)));
    }
}

// ------------------------------------------------- W3 permutation + tf32 ---
__global__ void perm_w3_kernel(const float* __restrict__ W3) {
    int idx = blockIdx.x * blockDim.x + threadIdx.x;   // < 128*4096
    int m  = idx >> 12;
    int np = idx & 4095;
    d_W3p[idx] = to_tf32(W3[(m << 12) + ((np & 63) << 6) + (np >> 6)]);
}

// ------------------------------------------------------------ SIREN stages --
__global__ void gen_h2_kernel(const float* __restrict__ W1,
                              const float* __restrict__ W2) {
    int l = blockIdx.x;     // 0..2047
    int j = threadIdx.x;    // 0..127
    __shared__ float h1[HID];
    float rel = -1.0f + 2.0f * (float)l / 2047.0f;
    h1[j] = sinf(30.0f * rel * W1[j]);
    __syncthreads();
    float acc = 0.0f;
#pragma unroll 16
    for (int m = 0; m < HID; m++)
        acc += h1[m] * W2[m * HID + j];
    d_h2T[j * LL + l] = sinf(30.0f * acc);   // transposed: [m][l]
}

// ------------------------------------------------------- radix-4 FFT core --
// N=4096 = 4^6, DIT, input base-4 digit-reversed, natural-order output.
// 512 threads, 2 radix-4 butterflies per thread per stage, 6 stages.
__device__ __forceinline__ int rev4(int d) {
    int r = __brev(d) >> 20;                       // 12-bit bit-reversal
    return ((r & 0x555) << 1) | ((r & 0xAAA) >> 1); // swap bit pairs -> digit rev
}

__device__ __forceinline__ float2 cmul(float2 a, float2 b) {
    return make_float2(a.x * b.x - a.y * b.y, a.x * b.y + a.y * b.x);
}

__device__ __forceinline__ void fft4_core(float2* buf) {
#pragma unroll
    for (int st = 0; st < 6; st++) {
        int q = 1 << (2 * st);
        int tstep = NFFT >> (2 * st + 2);
        __syncthreads();
#pragma unroll
        for (int k = 0; k < 2; k++) {
            int bf = threadIdx.x + (k << 9);               // 0..1023
            int j  = bf & (q - 1);
            int i0 = ((bf >> (2 * st)) << (2 * st + 2)) + j;
            float2 x0 = buf[i0];
            float2 x1 = buf[i0 + q];
            float2 x2 = buf[i0 + 2 * q];
            float2 x3 = buf[i0 + 3 * q];
            float2 u1 = cmul(x1, d_tw4[j * tstep]);
            float2 u2 = cmul(x2, d_tw4[2 * j * tstep]);
            float2 u3 = cmul(x3, d_tw4[3 * j * tstep]);
            float2 a  = make_float2(x0.x + u2.x, x0.y + u2.y);
            float2 b  = make_float2(x0.x - u2.x, x0.y - u2.y);
            float2 c  = make_float2(u1.x + u3.x, u1.y + u3.y);
            float2 dd = make_float2(u1.x - u3.x, u1.y - u3.y);
            buf[i0]         = make_float2(a.x + c.x,  a.y + c.y);
            buf[i0 + q]     = make_float2(b.x + dd.y, b.y - dd.x);  // b + (-i)d
            buf[i0 + 2 * q] = make_float2(a.x - c.x,  a.y - c.y);
            buf[i0 + 3 * q] = make_float2(b.x - dd.y, b.y + dd.x);  // b + (+i)d
        }
    }
    __syncthreads();
}

// FFT of time-reversed, zero-padded SIREN features: g[d] = h2[2047-d]
__global__ void fft_g_kernel() {
    __shared__ float2 buf[NFFT];
    int m = blockIdx.x;   // 0..127
    for (int d = threadIdx.x; d < NFFT; d += 512) {
        int src = rev4(d);
        float v = (src < LL) ? d_h2T[m * LL + (LL - 1 - src)] : 0.0f;
        buf[d] = make_float2(v, 0.0f);
    }
    fft4_core(buf);
    for (int f = threadIdx.x; f < NFFT; f += 512)
        d_Gf[m * NFFT + f] = make_float2(to_tf32(buf[f].x), to_tf32(buf[f].y));
}

// FFT of zero-padded inputs x[b,i,:]
__global__ void fft_x_kernel(const float* __restrict__ x) {
    __shared__ float2 buf[NFFT];
    int r = blockIdx.x;   // b*64+i
    for (int d = threadIdx.x; d < NFFT; d += 512) {
        int src = rev4(d);
        float v = (src < LL) ? x[r * LL + src] : 0.0f;
        buf[d] = make_float2(v, 0.0f);
    }
    fft4_core(buf);
    for (int f = threadIdx.x; f < NFFT; f += 512)
        d_Xf[r * NFFT + f] = buf[f];
}

// ------------------------------------- K4: kernel spectrum via tf32 MMA ----
// Kf[f][n] = Σ_m Gf[m][f] * W3p[m][n]  (complex A, real B), f tiles of 64,
// n tiles of 128, block = 8 warps: warp grid 2(f) x 4(n), warp tile 32x32.
#define MMA_TF32(C, A, B0, B1)                                              \
    asm volatile("mma.sync.aligned.m16n8k8.row.col.f32.tf32.tf32.f32 "      \
        "{%0,%1,%2,%3}, {%4,%5,%6,%7}, {%8,%9}, {%0,%1,%2,%3};"             \
        : "+f"(C[0]), "+f"(C[1]), "+f"(C[2]), "+f"(C[3])                    \
        : "r"(A[0]), "r"(A[1]), "r"(A[2]), "r"(A[3]), "r"(B0), "r"(B1))

__global__ void __launch_bounds__(256) k4_mma_kernel() {
    const int lane = threadIdx.x & 31;
    const int warp = threadIdx.x >> 5;           // 0..7
    const int g  = lane >> 2;                    // groupID (0..7)
    const int tg = lane & 3;                     // thread-in-group (0..3)
    const int fbase = blockIdx.y * 64 + (warp & 1) * 32;
    const int nbase = blockIdx.x * 128 + (warp >> 1) * 32;

    float cR[2][4][4], cI[2][4][4];
#pragma unroll
    for (int a = 0; a < 2; a++)
#pragma unroll
        for (int b = 0; b < 4; b++)
#pragma unroll
            for (int c = 0; c < 4; c++) { cR[a][b][c] = 0.f; cI[a][b][c] = 0.f; }

    for (int k0 = 0; k0 < HID; k0 += 8) {
        // --- B fragments (real, shared by both complex parts) ---
        unsigned b0[4], b1[4];
        const float* Br0 = d_W3p + (k0 + tg) * 4096;
        const float* Br1 = d_W3p + (k0 + tg + 4) * 4096;
#pragma unroll
        for (int j = 0; j < 4; j++) {
            int n = nbase + j * 8 + g;
            b0[j] = __float_as_uint(__ldg(&Br0[n]));
            b1[j] = __float_as_uint(__ldg(&Br1[n]));
        }
        // --- A fragments (complex): a0:(f,k) a1:(f+8,k) a2:(f,k+4) a3:(f+8,k+4)
        unsigned aR[2][4], aI[2][4];
#pragma unroll
        for (int mt = 0; mt < 2; mt++) {
            int f = fbase + mt * 16 + g;
            float2 v0 = __ldg(&d_Gf[(k0 + tg)     * NFFT + f]);
            float2 v1 = __ldg(&d_Gf[(k0 + tg)     * NFFT + f + 8]);
            float2 v2 = __ldg(&d_Gf[(k0 + tg + 4) * NFFT + f]);
            float2 v3 = __ldg(&d_Gf[(k0 + tg + 4) * NFFT + f + 8]);
            aR[mt][0] = __float_as_uint(v0.x); aI[mt][0] = __float_as_uint(v0.y);
            aR[mt][1] = __float_as_uint(v1.x); aI[mt][1] = __float_as_uint(v1.y);
            aR[mt][2] = __float_as_uint(v2.x); aI[mt][2] = __float_as_uint(v2.y);
            aR[mt][3] = __float_as_uint(v3.x); aI[mt][3] = __float_as_uint(v3.y);
        }
#pragma unroll
        for (int mt = 0; mt < 2; mt++)
#pragma unroll
            for (int j = 0; j < 4; j++) {
                MMA_TF32(cR[mt][j], aR[mt], b0[j], b1[j]);
                MMA_TF32(cI[mt][j], aI[mt], b0[j], b1[j]);
            }
    }
    // --- store: c0:(g,2tg) c1:(g,2tg+1) c2:(g+8,2tg) c3:(g+8,2tg+1) ---
#pragma unroll
    for (int mt = 0; mt < 2; mt++) {
#pragma unroll
        for (int rr = 0; rr < 2; rr++) {
            int f = fbase + mt * 16 + g + rr * 8;
            if (f < NBINS) {
#pragma unroll
                for (int j = 0; j < 4; j++) {
                    int n = nbase + j * 8 + tg * 2;
                    float4* p = (float4*)&d_Kf[(size_t)f * 4096 + n];
                    *p = make_float4(cR[mt][j][rr * 2], cI[mt][j][rr * 2],
                                     cR[mt][j][rr * 2 + 1], cI[mt][j][rr * 2 + 1]);
                }
            }
        }
    }
}

// ---------------------------------------- K5: per-bin 64x64 complex mixing --
// Outf[b,o,f] = Σ_i Xf[b,i,f] * Kf[f][i*64+o]
__global__ void k5_mix_kernel() {
    __shared__ float2 Xs[128];
    int f = blockIdx.x;          // 0..2048
    int t = threadIdx.x;         // 0..127
    Xs[t] = d_Xf[t * NFFT + f];
    __syncthreads();
    int b = t >> 6, o = t & 63;
    const float2* kf = &d_Kf[(size_t)f * 4096 + o];
    const float2* xs = &Xs[b * 64];
    float ar = 0.0f, ai = 0.0f;
#pragma unroll 8
    for (int i = 0; i < 64; i++) {
        float2 xv = xs[i];
        float2 kv = kf[i * 64];
        ar += xv.x * kv.x - xv.y * kv.y;
        ai += xv.x * kv.y + xv.y * kv.x;
    }
    d_Outf[t * NBINS + f] = make_float2(ar, ai);
}

// --------------------------------- inverse FFT (Hermitian extend + conj) ---
__global__ void fft_inv_kernel(float* __restrict__ out) {
    __shared__ float2 buf[NFFT];
    int r = blockIdx.x;   // b*64+o
    for (int d = threadIdx.x; d < NFFT; d += 512) {
        int src = rev4(d);
        float2 v;
        if (src <= 2048) {
            float2 tval = d_Outf[r * NBINS + src];
            v = make_float2(tval.x, -tval.y);          // conj
        } else {
            v = d_Outf[r * NBINS + (NFFT - src)];      // conj(conj(.)) = .
        }
        buf[d] = v;
    }
    fft4_core(buf);
    const float inv = 1.0f / (float)NFFT;
    for (int t = threadIdx.x; t < LL; t += 512)
        out[r * LL + t] = buf[t].x * inv;
}

// ============================================================================
extern "C" void kernel_launch(void* const* d_in, const int* in_sizes, int n_in,
                              void* d_out, int out_size) {
    (void)in_sizes; (void)n_in; (void)out_size;
    const float* x  = (const float*)d_in[0];
    const float* W1 = (const float*)d_in[1];
    const float* W2 = (const float*)d_in[2];
    const float* W3 = (const float*)d_in[3];
    float* out = (float*)d_out;

    init_tw_kernel<<<16, 256>>>();
    perm_w3_kernel<<<2048, 256>>>(W3);
    gen_h2_kernel<<<2048, 128>>>(W1, W2);
    fft_g_kernel<<<128, 512>>>();
    fft_x_kernel<<<128, 512>>>(x);
    k4_mma_kernel<<<dim3(32, 33), 256>>>();
    k5_mix_kernel<<<NBINS, 128>>>();
    fft_inv_kernel<<<128, 512>>>(out);
}